// round 7
// baseline (speedup 1.0000x reference)
#include <cuda_runtime.h>
#include <cuda_fp16.h>

#define NN   50000
#define DD   128
#define NV2  (NN * DD / 4)      // uint2 (4 halves) per T slot = 1.6M
#define NNZ_CAP 800000
#define MCAP 32

#define SPMM_BLOCKS 1184        // 148 SMs x 8 blocks, 256 thr -> single wave
#define SPMM_THREADS 256

// ---- static scratch (allocation-free rule: __device__ globals) ----
__device__ __half g_T[MCAP * NN * DD];   // all Chebyshev iterates, fp16 (slot k = T_k)
__device__ int   g_cnt[NN];
__device__ int   g_rptr[NN + 1];
__device__ int   g_cursor[NN];
__device__ int2  g_edges[NNZ_CAP];       // {col, val-as-int}

// ---------------- CSR build ----------------
__global__ void hist_kernel(const int* __restrict__ rows, int nnz) {
    int i = blockIdx.x * blockDim.x + threadIdx.x;
    if (i < nnz) atomicAdd(&g_cnt[rows[i]], 1);
}

__global__ void scan_kernel(int nnz) {
    __shared__ int sh[1024];
    const int t  = threadIdx.x;
    const int CH = (NN + 1023) / 1024;
    const int base = t * CH;

    int sum = 0;
    #pragma unroll 4
    for (int i = 0; i < CH; i++) {
        int idx = base + i;
        if (idx < NN) sum += g_cnt[idx];
    }
    sh[t] = sum;
    __syncthreads();

    for (int d = 1; d < 1024; d <<= 1) {
        int v = (t >= d) ? sh[t - d] : 0;
        __syncthreads();
        sh[t] += v;
        __syncthreads();
    }

    int off = sh[t] - sum;   // exclusive prefix for this chunk
    for (int i = 0; i < CH; i++) {
        int idx = base + i;
        if (idx < NN) {
            g_rptr[idx]   = off;
            g_cursor[idx] = off;
            off += g_cnt[idx];
        }
    }
    if (t == 1023) g_rptr[NN] = nnz;
}

__global__ void scatter_kernel(const int* __restrict__ rows,
                               const int* __restrict__ cols,
                               const float* __restrict__ vals, int nnz) {
    int i = blockIdx.x * blockDim.x + threadIdx.x;
    if (i < nnz) {
        int r = rows[i];
        int p = atomicAdd(&g_cursor[r], 1);
        g_edges[p] = make_int2(cols[i], __float_as_int(vals[i]));
    }
}

// ---------------- fp32 -> fp16 convert (X -> slot 0) ----------------
__global__ void convert_kernel(const float* __restrict__ X, __half* __restrict__ H) {
    int i = blockIdx.x * blockDim.x + threadIdx.x;          // 4 elems per thread
    if (i < NV2) {
        float4 v = __ldg(&((const float4*)X)[i]);
        __half2 lo = __floats2half2_rn(v.x, v.y);
        __half2 hi = __floats2half2_rn(v.z, v.w);
        uint2 r;
        r.x = *(unsigned int*)&lo;
        r.y = *(unsigned int*)&hi;
        ((uint2*)H)[i] = r;
    }
}

// ---------------- helpers ----------------
__device__ __forceinline__ void fma_h(float4& a, uint2 r, float v) {
    float2 lo = __half22float2(*(const __half2*)&r.x);
    float2 hi = __half22float2(*(const __half2*)&r.y);
    a.x += v * lo.x; a.y += v * lo.y; a.z += v * hi.x; a.w += v * hi.y;
}

__device__ __forceinline__ uint2 pack_h(float4 t) {
    __half2 lo = __floats2half2_rn(t.x, t.y);
    __half2 hi = __floats2half2_rn(t.z, t.w);
    uint2 r;
    r.x = *(unsigned int*)&lo;
    r.y = *(unsigned int*)&hi;
    return r;
}

__device__ __forceinline__ float4 spmm_row_h(const __half* __restrict__ T,
                                             int s, int e, int lane) {
    float4 a = make_float4(0.f, 0.f, 0.f, 0.f);
    const uint2* Tv = (const uint2*)T;    // 4 halves per uint2; row stride = 32
    int i = s;
    // unroll-by-4: keep 4 gathers + 4 edge loads outstanding (MLP)
    for (; i + 3 < e; i += 4) {
        int2 e0 = __ldg(&g_edges[i]);
        int2 e1 = __ldg(&g_edges[i + 1]);
        int2 e2 = __ldg(&g_edges[i + 2]);
        int2 e3 = __ldg(&g_edges[i + 3]);
        uint2 r0 = __ldg(&Tv[e0.x * 32 + lane]);
        uint2 r1 = __ldg(&Tv[e1.x * 32 + lane]);
        uint2 r2 = __ldg(&Tv[e2.x * 32 + lane]);
        uint2 r3 = __ldg(&Tv[e3.x * 32 + lane]);
        fma_h(a, r0, __int_as_float(e0.y));
        fma_h(a, r1, __int_as_float(e1.y));
        fma_h(a, r2, __int_as_float(e2.y));
        fma_h(a, r3, __int_as_float(e3.y));
    }
    for (; i < e; i++) {
        int2 e0 = __ldg(&g_edges[i]);
        uint2 r0 = __ldg(&Tv[e0.x * 32 + lane]);
        fma_h(a, r0, __int_as_float(e0.y));
    }
    return a;
}

// T1 = L @ T0 (slot0 -> slot1); single-wave grid, warp loops over rows
__global__ void __launch_bounds__(SPMM_THREADS)
cheb_first(const __half* __restrict__ T0, __half* __restrict__ T1) {
    const int lane   = threadIdx.x & 31;
    const int warp0  = (blockIdx.x * blockDim.x + threadIdx.x) >> 5;
    const int nwarps = (gridDim.x * blockDim.x) >> 5;

    for (int gw = warp0; gw < NN; gw += nwarps) {
        int s = g_rptr[gw], e = g_rptr[gw + 1];
        float4 a = spmm_row_h(T0, s, e, lane);
        ((uint2*)T1)[gw * 32 + lane] = pack_h(a);
    }
}

// Tk = 2*(L @ Tc) - Tp ; single-wave grid, warp loops over rows
__global__ void __launch_bounds__(SPMM_THREADS)
cheb_step(const __half* __restrict__ Tc,
          const __half* __restrict__ Tp,
          __half* __restrict__ Tn) {
    const int lane   = threadIdx.x & 31;
    const int warp0  = (blockIdx.x * blockDim.x + threadIdx.x) >> 5;
    const int nwarps = (gridDim.x * blockDim.x) >> 5;

    for (int gw = warp0; gw < NN; gw += nwarps) {
        int s = g_rptr[gw], e = g_rptr[gw + 1];
        float4 a = spmm_row_h(Tc, s, e, lane);

        int idx = gw * 32 + lane;
        uint2 tpr = __ldg(&((const uint2*)Tp)[idx]);
        float2 tplo = __half22float2(*(const __half2*)&tpr.x);
        float2 tphi = __half22float2(*(const __half2*)&tpr.y);

        float4 tk;
        tk.x = 2.f * a.x - tplo.x;
        tk.y = 2.f * a.y - tplo.y;
        tk.z = 2.f * a.z - tphi.x;
        tk.w = 2.f * a.w - tphi.y;
        ((uint2*)Tn)[idx] = pack_h(tk);
    }
}

// out = sum_k coeffs[k] * T_k   (single streaming pass over all slots)
__global__ void __launch_bounds__(SPMM_THREADS)
reduce_kernel(const __half* __restrict__ T,
              const float* __restrict__ coeffs,
              float* __restrict__ out, int M) {
    const int stride = gridDim.x * blockDim.x;
    const uint2* base = (const uint2*)T;
    for (int i = blockIdx.x * blockDim.x + threadIdx.x; i < NV2; i += stride) {
        float4 a = make_float4(0.f, 0.f, 0.f, 0.f);
        int k = 0;
        for (; k + 3 < M; k += 4) {
            uint2 r0 = __ldg(&base[(size_t)(k + 0) * NV2 + i]);
            uint2 r1 = __ldg(&base[(size_t)(k + 1) * NV2 + i]);
            uint2 r2 = __ldg(&base[(size_t)(k + 2) * NV2 + i]);
            uint2 r3 = __ldg(&base[(size_t)(k + 3) * NV2 + i]);
            fma_h(a, r0, __ldg(&coeffs[k + 0]));
            fma_h(a, r1, __ldg(&coeffs[k + 1]));
            fma_h(a, r2, __ldg(&coeffs[k + 2]));
            fma_h(a, r3, __ldg(&coeffs[k + 3]));
        }
        for (; k < M; k++) {
            uint2 r = __ldg(&base[(size_t)k * NV2 + i]);
            fma_h(a, r, __ldg(&coeffs[k]));
        }
        ((float4*)out)[i] = a;
    }
}

// ---------------- launch ----------------
extern "C" void kernel_launch(void* const* d_in, const int* in_sizes, int n_in,
                              void* d_out, int out_size) {
    const int*   rows   = (const int*)d_in[0];
    const int*   cols   = (const int*)d_in[1];
    const float* vals   = (const float*)d_in[2];
    const float* X      = (const float*)d_in[3];
    const float* coeffs = (const float*)d_in[4];
    const int nnz = in_sizes[0];
    const int M   = in_sizes[4];

    void* p;
    __half* T;
    int* pcnt;
    cudaGetSymbolAddress(&p, g_T);   T = (__half*)p;
    cudaGetSymbolAddress(&p, g_cnt); pcnt = (int*)p;

    const size_t SLOT = (size_t)NN * DD;

    // ---- CSR build (in-graph, re-done every replay) ----
    cudaMemsetAsync(pcnt, 0, NN * sizeof(int));
    hist_kernel<<<(nnz + 255) / 256, 256>>>(rows, nnz);
    scan_kernel<<<1, 1024>>>(nnz);
    scatter_kernel<<<(nnz + 255) / 256, 256>>>(rows, cols, vals, nnz);

    // ---- X -> fp16 slot 0 ----
    convert_kernel<<<(NV2 + 255) / 256, 256>>>(X, T);

    // ---- Chebyshev recurrence: slot k = T_k (single-wave launches) ----
    cheb_first<<<SPMM_BLOCKS, SPMM_THREADS>>>(T, T + SLOT);
    for (int k = 2; k < M; k++) {
        cheb_step<<<SPMM_BLOCKS, SPMM_THREADS>>>(T + (size_t)(k - 1) * SLOT,
                                                 T + (size_t)(k - 2) * SLOT,
                                                 T + (size_t)k * SLOT);
    }

    // ---- final weighted reduction ----
    reduce_kernel<<<SPMM_BLOCKS, SPMM_THREADS>>>(T, coeffs, (float*)d_out, M);
}

// round 8
// speedup vs baseline: 1.1086x; 1.1086x over previous
#include <cuda_runtime.h>
#include <cuda_fp16.h>

#define NN   50000
#define DD   128
#define NV2  (NN * DD / 4)      // uint2 (4 halves) per T slot = 1.6M
#define NNZ_CAP 800000
#define MCAP 32

// ---- static scratch (allocation-free rule: __device__ globals) ----
__device__ __half g_T[MCAP * NN * DD];   // all Chebyshev iterates, fp16 (slot k = T_k)
__device__ int   g_cnt[NN];
__device__ int   g_rptr[NN + 1];
__device__ int   g_cursor[NN];
__device__ int2  g_edges[NNZ_CAP];       // {col, val-as-int}

// ---------------- CSR build ----------------
__global__ void hist_kernel(const int* __restrict__ rows, int nnz) {
    int i = blockIdx.x * blockDim.x + threadIdx.x;
    if (i < nnz) atomicAdd(&g_cnt[rows[i]], 1);
}

__global__ void scan_kernel(int nnz) {
    __shared__ int sh[1024];
    const int t  = threadIdx.x;
    const int CH = (NN + 1023) / 1024;
    const int base = t * CH;

    int sum = 0;
    #pragma unroll 4
    for (int i = 0; i < CH; i++) {
        int idx = base + i;
        if (idx < NN) sum += g_cnt[idx];
    }
    sh[t] = sum;
    __syncthreads();

    for (int d = 1; d < 1024; d <<= 1) {
        int v = (t >= d) ? sh[t - d] : 0;
        __syncthreads();
        sh[t] += v;
        __syncthreads();
    }

    int off = sh[t] - sum;   // exclusive prefix for this chunk
    for (int i = 0; i < CH; i++) {
        int idx = base + i;
        if (idx < NN) {
            g_rptr[idx]   = off;
            g_cursor[idx] = off;
            off += g_cnt[idx];
        }
    }
    if (t == 1023) g_rptr[NN] = nnz;
}

__global__ void scatter_kernel(const int* __restrict__ rows,
                               const int* __restrict__ cols,
                               const float* __restrict__ vals, int nnz) {
    int i = blockIdx.x * blockDim.x + threadIdx.x;
    if (i < nnz) {
        int r = rows[i];
        int p = atomicAdd(&g_cursor[r], 1);
        g_edges[p] = make_int2(cols[i], __float_as_int(vals[i]));
    }
}

// ---------------- fp32 -> fp16 convert (X -> slot 0) ----------------
__global__ void convert_kernel(const float* __restrict__ X, __half* __restrict__ H) {
    int i = blockIdx.x * blockDim.x + threadIdx.x;          // 4 elems per thread
    if (i < NV2) {
        float4 v = __ldg(&((const float4*)X)[i]);
        __half2 lo = __floats2half2_rn(v.x, v.y);
        __half2 hi = __floats2half2_rn(v.z, v.w);
        uint2 r;
        r.x = *(unsigned int*)&lo;
        r.y = *(unsigned int*)&hi;
        ((uint2*)H)[i] = r;
    }
}

// ---------------- helpers ----------------
__device__ __forceinline__ void fma_h(float4& a, uint2 r, float v) {
    float2 lo = __half22float2(*(const __half2*)&r.x);
    float2 hi = __half22float2(*(const __half2*)&r.y);
    a.x += v * lo.x; a.y += v * lo.y; a.z += v * hi.x; a.w += v * hi.y;
}

__device__ __forceinline__ uint2 pack_h(float4 t) {
    __half2 lo = __floats2half2_rn(t.x, t.y);
    __half2 hi = __floats2half2_rn(t.z, t.w);
    uint2 r;
    r.x = *(unsigned int*)&lo;
    r.y = *(unsigned int*)&hi;
    return r;
}

// SpMM for one row; all 32 lanes cooperatively prefetch up to 32 edges in ONE
// coalesced load, then shfl-broadcast (col,val). All gathers for the chunk are
// address-ready immediately -> deep MLP (unroll 8).
__device__ __forceinline__ float4 spmm_row_h(const __half* __restrict__ T,
                                             int s, int e, int lane) {
    float4 a = make_float4(0.f, 0.f, 0.f, 0.f);
    const uint2* Tv = (const uint2*)T;    // 4 halves per uint2; row stride = 32

    for (int base = s; base < e; base += 32) {
        const int n = min(32, e - base);
        int2 ed = make_int2(0, 0);
        if (base + lane < e) ed = __ldg(&g_edges[base + lane]);
        const int ecol = ed.x;
        const int eval = ed.y;

        int j = 0;
        for (; j + 7 < n; j += 8) {
            int c0 = __shfl_sync(0xffffffffu, ecol, j + 0);
            int c1 = __shfl_sync(0xffffffffu, ecol, j + 1);
            int c2 = __shfl_sync(0xffffffffu, ecol, j + 2);
            int c3 = __shfl_sync(0xffffffffu, ecol, j + 3);
            int c4 = __shfl_sync(0xffffffffu, ecol, j + 4);
            int c5 = __shfl_sync(0xffffffffu, ecol, j + 5);
            int c6 = __shfl_sync(0xffffffffu, ecol, j + 6);
            int c7 = __shfl_sync(0xffffffffu, ecol, j + 7);
            uint2 r0 = __ldg(&Tv[c0 * 32 + lane]);
            uint2 r1 = __ldg(&Tv[c1 * 32 + lane]);
            uint2 r2 = __ldg(&Tv[c2 * 32 + lane]);
            uint2 r3 = __ldg(&Tv[c3 * 32 + lane]);
            uint2 r4 = __ldg(&Tv[c4 * 32 + lane]);
            uint2 r5 = __ldg(&Tv[c5 * 32 + lane]);
            uint2 r6 = __ldg(&Tv[c6 * 32 + lane]);
            uint2 r7 = __ldg(&Tv[c7 * 32 + lane]);
            fma_h(a, r0, __int_as_float(__shfl_sync(0xffffffffu, eval, j + 0)));
            fma_h(a, r1, __int_as_float(__shfl_sync(0xffffffffu, eval, j + 1)));
            fma_h(a, r2, __int_as_float(__shfl_sync(0xffffffffu, eval, j + 2)));
            fma_h(a, r3, __int_as_float(__shfl_sync(0xffffffffu, eval, j + 3)));
            fma_h(a, r4, __int_as_float(__shfl_sync(0xffffffffu, eval, j + 4)));
            fma_h(a, r5, __int_as_float(__shfl_sync(0xffffffffu, eval, j + 5)));
            fma_h(a, r6, __int_as_float(__shfl_sync(0xffffffffu, eval, j + 6)));
            fma_h(a, r7, __int_as_float(__shfl_sync(0xffffffffu, eval, j + 7)));
        }
        for (; j + 1 < n; j += 2) {
            int c0 = __shfl_sync(0xffffffffu, ecol, j + 0);
            int c1 = __shfl_sync(0xffffffffu, ecol, j + 1);
            uint2 r0 = __ldg(&Tv[c0 * 32 + lane]);
            uint2 r1 = __ldg(&Tv[c1 * 32 + lane]);
            fma_h(a, r0, __int_as_float(__shfl_sync(0xffffffffu, eval, j + 0)));
            fma_h(a, r1, __int_as_float(__shfl_sync(0xffffffffu, eval, j + 1)));
        }
        if (j < n) {
            int c0 = __shfl_sync(0xffffffffu, ecol, j);
            uint2 r0 = __ldg(&Tv[c0 * 32 + lane]);
            fma_h(a, r0, __int_as_float(__shfl_sync(0xffffffffu, eval, j)));
        }
    }
    return a;
}

// T1 = L @ T0 (slot0 -> slot1); one row per warp
__global__ void cheb_first(const __half* __restrict__ T0,
                           __half* __restrict__ T1) {
    int gw   = (blockIdx.x * blockDim.x + threadIdx.x) >> 5;
    int lane = threadIdx.x & 31;
    if (gw >= NN) return;
    int s = g_rptr[gw], e = g_rptr[gw + 1];

    float4 a = spmm_row_h(T0, s, e, lane);
    ((uint2*)T1)[gw * 32 + lane] = pack_h(a);
}

// Tk = 2*(L @ Tc) - Tp  (slot k-1, slot k-2 -> slot k); one row per warp
__global__ void cheb_step(const __half* __restrict__ Tc,
                          const __half* __restrict__ Tp,
                          __half* __restrict__ Tn) {
    int gw   = (blockIdx.x * blockDim.x + threadIdx.x) >> 5;
    int lane = threadIdx.x & 31;
    if (gw >= NN) return;
    int s = g_rptr[gw], e = g_rptr[gw + 1];

    float4 a = spmm_row_h(Tc, s, e, lane);

    int idx = gw * 32 + lane;
    uint2 tpr = __ldg(&((const uint2*)Tp)[idx]);
    float2 tplo = __half22float2(*(const __half2*)&tpr.x);
    float2 tphi = __half22float2(*(const __half2*)&tpr.y);

    float4 tk;
    tk.x = 2.f * a.x - tplo.x;
    tk.y = 2.f * a.y - tplo.y;
    tk.z = 2.f * a.z - tphi.x;
    tk.w = 2.f * a.w - tphi.y;
    ((uint2*)Tn)[idx] = pack_h(tk);
}

// out = sum_k coeffs[k] * T_k   (single streaming pass over all slots)
__global__ void reduce_kernel(const __half* __restrict__ T,
                              const float* __restrict__ coeffs,
                              float* __restrict__ out, int M) {
    int i = blockIdx.x * blockDim.x + threadIdx.x;
    if (i >= NV2) return;
    const uint2* base = (const uint2*)T;
    float4 a = make_float4(0.f, 0.f, 0.f, 0.f);
    int k = 0;
    for (; k + 3 < M; k += 4) {
        uint2 r0 = __ldg(&base[(size_t)(k + 0) * NV2 + i]);
        uint2 r1 = __ldg(&base[(size_t)(k + 1) * NV2 + i]);
        uint2 r2 = __ldg(&base[(size_t)(k + 2) * NV2 + i]);
        uint2 r3 = __ldg(&base[(size_t)(k + 3) * NV2 + i]);
        fma_h(a, r0, __ldg(&coeffs[k + 0]));
        fma_h(a, r1, __ldg(&coeffs[k + 1]));
        fma_h(a, r2, __ldg(&coeffs[k + 2]));
        fma_h(a, r3, __ldg(&coeffs[k + 3]));
    }
    for (; k < M; k++) {
        uint2 r = __ldg(&base[(size_t)k * NV2 + i]);
        fma_h(a, r, __ldg(&coeffs[k]));
    }
    ((float4*)out)[i] = a;
}

// ---------------- launch ----------------
extern "C" void kernel_launch(void* const* d_in, const int* in_sizes, int n_in,
                              void* d_out, int out_size) {
    const int*   rows   = (const int*)d_in[0];
    const int*   cols   = (const int*)d_in[1];
    const float* vals   = (const float*)d_in[2];
    const float* X      = (const float*)d_in[3];
    const float* coeffs = (const float*)d_in[4];
    const int nnz = in_sizes[0];
    const int M   = in_sizes[4];

    void* p;
    __half* T;
    int* pcnt;
    cudaGetSymbolAddress(&p, g_T);   T = (__half*)p;
    cudaGetSymbolAddress(&p, g_cnt); pcnt = (int*)p;

    const size_t SLOT = (size_t)NN * DD;

    // ---- CSR build (in-graph, re-done every replay) ----
    cudaMemsetAsync(pcnt, 0, NN * sizeof(int));
    hist_kernel<<<(nnz + 255) / 256, 256>>>(rows, nnz);
    scan_kernel<<<1, 1024>>>(nnz);
    scatter_kernel<<<(nnz + 255) / 256, 256>>>(rows, cols, vals, nnz);

    // ---- X -> fp16 slot 0 ----
    convert_kernel<<<(NV2 + 255) / 256, 256>>>(X, T);

    // ---- Chebyshev recurrence: slot k = T_k (one row per warp) ----
    const int threads = 256;                 // 8 rows per block
    const int rowsPerBlk = threads / 32;
    const int grid = (NN + rowsPerBlk - 1) / rowsPerBlk;

    cheb_first<<<grid, threads>>>(T, T + SLOT);
    for (int k = 2; k < M; k++) {
        cheb_step<<<grid, threads>>>(T + (size_t)(k - 1) * SLOT,
                                     T + (size_t)(k - 2) * SLOT,
                                     T + (size_t)k * SLOT);
    }

    // ---- final weighted reduction ----
    reduce_kernel<<<(NV2 + 255) / 256, 256>>>(T, coeffs, (float*)d_out, M);
}